// round 7
// baseline (speedup 1.0000x reference)
#include <cuda_runtime.h>
#include <stdint.h>

#define B 8
#define H 1024
#define W 1024
#define NPIX (H * W)
#define SAL_ELEMS (B * 3 * NPIX)
#define NPAIRS (H * (W - 1))
#define MAXAB 64                   // >= actual merged band count (~52)

// ---------------- scratch ----------------
__device__ int g_bstart[MAXAB + 1];           // merged band start rows + sentinel
__device__ int g_nab;
__device__ float g_aband[B * MAXAB * W];      // [b][atomic band][col], 2 MB
__device__ unsigned g_d2part[B * 64];
__device__ int g_tier[B];
__device__ float g_segmean[B * 3 * 256];

// tier x map geometry: n = BASE[t]+(m-1)*INCR[t]; gr=round(sqrt n); gc=ceil(n/gr)
__constant__ int c_gr[3][3] = { {4, 5, 6}, {8, 9, 10}, {11, 12, 13} };
__constant__ int c_gc[3][3] = { {5, 6, 7}, {9, 9, 10}, {12, 13, 14} };
__constant__ int c_base[3] = { 30, 80, 150 };
__constant__ int c_incr[3] = { 10, 15, 25 };

// ---------------- K_tables: build merged row-band boundary list ----------------
__global__ void k_tables() {
    const int grs[9] = { 4, 5, 6, 8, 9, 10, 11, 12, 13 };
    int row = threadIdx.x;            // 1024 threads
    bool flag = (row == 0);
    if (!flag) {
#pragma unroll
        for (int i = 0; i < 9; i++) {
            int g = grs[i];
            if (((row * g) >> 10) != (((row - 1) * g) >> 10)) { flag = true; break; }
        }
    }
    __shared__ unsigned s_bal[32];
    unsigned bal = __ballot_sync(0xFFFFFFFFu, flag);
    int warp = row >> 5, lane = row & 31;
    if (lane == 0) s_bal[warp] = bal;
    __syncthreads();
    if (flag) {
        int idx = __popc(bal & ((1u << lane) - 1));
        for (int w = 0; w < warp; w++) idx += __popc(s_bal[w]);
        g_bstart[idx] = row;
    }
    if (row == 0) {
        int tot = 0;
        for (int w = 0; w < 32; w++) tot += __popc(s_bal[w]);
        g_nab = tot;
    }
    __syncthreads();
    if (row == 0) g_bstart[g_nab] = H;
}

// ---------------- K_zero: zero atomic-band accumulators ----------------
__global__ __launch_bounds__(256) void k_zero() {
    int i = blockIdx.x * 256 + threadIdx.x;     // float4 index; 512*256 = exact
    ((float4*)g_aband)[i] = make_float4(0.f, 0.f, 0.f, 0.f);
}

// ---------------- K1: fused gray + complexity + row-band sums ----------------
// Block = (b, 16-row chunk). 256 threads x 4 cols, float4 streaming loads.
// chan_mean never touches DRAM: per-thread accumulators flush to g_aband
// only at merged band boundaries (~2 flushes per thread).
__global__ __launch_bounds__(256) void k_gray(const float* __restrict__ img) {
    __shared__ int s_bs[MAXAB + 1];
    __shared__ unsigned s_w[8];

    int chunk = blockIdx.x & 63;
    int b = blockIdx.x >> 6;
    int rc0 = chunk << 4;
    int t = threadIdx.x;
    int col = t << 2;
    int lane = t & 31;
    unsigned mask = 0xFFFFFFFFu;

    if (t <= MAXAB) s_bs[t] = g_bstart[t];
    __syncthreads();

    // locate atomic band containing rc0 (sentinel s_bs[nab]=H bounds the walk)
    int ab = 0;
    while (s_bs[ab + 1] <= rc0) ab++;
    int next = s_bs[ab + 1];

    float4 acc = make_float4(0.f, 0.f, 0.f, 0.f);
    bool dirty = false;
    unsigned d2 = 0;
    float* abandb = g_aband + (size_t)b * MAXAB * W + col;

    const float* base = img + (size_t)b * 3 * NPIX + col;

#pragma unroll 4
    for (int rr = 0; rr < 16; rr++) {
        int r = rc0 + rr;
        const float* p = base + (size_t)r * W;
        float4 r4 = __ldcs((const float4*)p);
        float4 g4 = __ldcs((const float4*)(p + NPIX));
        float4 b4 = __ldcs((const float4*)(p + 2 * NPIX));

        float gy0 = 0.299f * r4.x + 0.587f * g4.x + 0.114f * b4.x;
        float gy1 = 0.299f * r4.y + 0.587f * g4.y + 0.114f * b4.y;
        float gy2 = 0.299f * r4.z + 0.587f * g4.z + 0.114f * b4.z;
        float gy3 = 0.299f * r4.w + 0.587f * g4.w + 0.114f * b4.w;

        acc.x += (r4.x + g4.x + b4.x) * (1.0f / 3.0f);
        acc.y += (r4.y + g4.y + b4.y) * (1.0f / 3.0f);
        acc.z += (r4.z + g4.z + b4.z) * (1.0f / 3.0f);
        acc.w += (r4.w + g4.w + b4.w) * (1.0f / 3.0f);
        dirty = true;

        float gnext = __shfl_down_sync(mask, gy0, 1);
        if (lane == 31 && col + 4 < W) {
            const float* q = p + 4;
            gnext = 0.299f * q[0] + 0.587f * q[NPIX] + 0.114f * q[2 * NPIX];
        }

        int i0 = min(max((int)(gy0 * 255.0f), 0), 255);
        int i1 = min(max((int)(gy1 * 255.0f), 0), 255);
        int i2 = min(max((int)(gy2 * 255.0f), 0), 255);
        int i3 = min(max((int)(gy3 * 255.0f), 0), 255);

        int d;
        d = i0 - i1; d2 += (unsigned)(d * d);
        d = i1 - i2; d2 += (unsigned)(d * d);
        d = i2 - i3; d2 += (unsigned)(d * d);
        if (col + 3 < W - 1) {
            int i4 = min(max((int)(gnext * 255.0f), 0), 255);
            d = i3 - i4; d2 += (unsigned)(d * d);
        }

        if (r + 1 == next) {
            float* dst = abandb + (size_t)ab * W;
            atomicAdd(dst + 0, acc.x);
            atomicAdd(dst + 1, acc.y);
            atomicAdd(dst + 2, acc.z);
            atomicAdd(dst + 3, acc.w);
            acc = make_float4(0.f, 0.f, 0.f, 0.f);
            dirty = false;
            ab++;
            next = s_bs[ab + 1];
        }
    }
    if (dirty) {
        float* dst = abandb + (size_t)ab * W;
        atomicAdd(dst + 0, acc.x);
        atomicAdd(dst + 1, acc.y);
        atomicAdd(dst + 2, acc.z);
        atomicAdd(dst + 3, acc.w);
    }

    // block-reduce d2 -> one partial per chunk
    d2 = __reduce_add_sync(mask, d2);
    if (lane == 0) s_w[t >> 5] = d2;
    __syncthreads();
    if (t == 0) {
        unsigned tot = 0;
#pragma unroll
        for (int i = 0; i < 8; i++) tot += s_w[i];
        g_d2part[blockIdx.x] = tot;
    }
}

// ---------------- K2: complexity -> tier; scalar tail ----------------
__global__ __launch_bounds__(64) void k_tier(float* __restrict__ out, int write_tail) {
    int b = blockIdx.x;
    int t = threadIdx.x;    // 64 threads
    unsigned long long s = (unsigned long long)g_d2part[b * 64 + t];
#pragma unroll
    for (int o = 16; o > 0; o >>= 1) s += __shfl_down_sync(0xFFFFFFFFu, s, o);
    __shared__ unsigned long long sw[2];
    if ((t & 31) == 0) sw[t >> 5] = s;
    __syncthreads();
    if (t == 0) {
        unsigned long long tot = sw[0] + sw[1];
        float comp = (float)tot / (float)NPAIRS;
        int tier = (comp < 50.0f) ? 0 : ((comp < 150.0f) ? 1 : 2);
        g_tier[b] = tier;
        if (write_tail) {
            out[SAL_ELEMS + b] = comp;
#pragma unroll
            for (int m = 0; m < 3; m++)
                out[SAL_ELEMS + B + b * 3 + m] = (float)(c_base[tier] + (m - 1) * c_incr[tier]);
        }
    }
}

// ---------------- K3: segment means from atomic-band sums ----------------
// Variant boundaries are a subset of merged boundaries, so atomic bands
// exactly tile each segment's row range.
__global__ __launch_bounds__(32) void k_segmean() {
    int b = blockIdx.z, m = blockIdx.y, seg = blockIdx.x;
    int tier = g_tier[b];
    int gr = c_gr[tier][m], gc = c_gc[tier][m];
    if (seg >= gr * gc) return;
    int r = seg / gc, c = seg - r * gc;
    int r0 = (r * H + gr - 1) / gr;
    int r1 = ((r + 1) * H + gr - 1) / gr; if (r1 > H) r1 = H;
    int c0 = (c * W + gc - 1) / gc;
    int c1 = ((c + 1) * W + gc - 1) / gc; if (c1 > W) c1 = W;

    int nab = g_nab;
    int lane = threadIdx.x;
    float s = 0.0f;
    for (int ab = 0; ab < nab; ab++) {
        int bs = g_bstart[ab];
        if (bs >= r0 && bs < r1) {
            const float* p = g_aband + ((size_t)b * MAXAB + ab) * W;
            for (int col = c0 + lane; col < c1; col += 32) s += p[col];
        }
    }
#pragma unroll
    for (int o = 16; o > 0; o >>= 1) s += __shfl_down_sync(0xFFFFFFFFu, s, o);
    if (lane == 0) {
        int cnt = (r1 - r0) * (c1 - c0);
        g_segmean[((size_t)b * 3 + m) * 256 + seg] = s / (float)cnt;
    }
}

// ---------------- K4: fill saliency (streaming float4 stores) ----------------
__global__ __launch_bounds__(256) void k_fill(float* __restrict__ out) {
    int idx = blockIdx.x * blockDim.x + threadIdx.x;
    int bm = idx >> 18;
    int within = idx & 262143;
    int row = within >> 8;
    int col = (within & 255) << 2;

    int b = bm / 3;
    int m = bm - b * 3;
    int tier = g_tier[b];
    int gr = c_gr[tier][m], gc = c_gc[tier][m];
    const float* sm = g_segmean + (size_t)bm * 256;

    int rb = (row * gr) >> 10;
    int basei = rb * gc;
    float4 v;
    v.x = sm[basei + (((col + 0) * gc) >> 10)];
    v.y = sm[basei + (((col + 1) * gc) >> 10)];
    v.z = sm[basei + (((col + 2) * gc) >> 10)];
    v.w = sm[basei + (((col + 3) * gc) >> 10)];
    __stcs((float4*)(out + (size_t)bm * NPIX + (size_t)row * W + col), v);
}

// ---------------- launch ----------------
extern "C" void kernel_launch(void* const* d_in, const int* in_sizes, int n_in,
                              void* d_out, int out_size) {
    const float* img = (const float*)d_in[0];
    float* out = (float*)d_out;
    int write_tail = (out_size >= SAL_ELEMS + B + B * 3) ? 1 : 0;

    k_tables<<<1, 1024>>>();
    k_zero<<<512, 256>>>();
    k_gray<<<B * 64, 256>>>(img);
    k_tier<<<B, 64>>>(out, write_tail);
    dim3 gsm(182, 3, B);
    k_segmean<<<gsm, 32>>>();
    k_fill<<<(SAL_ELEMS / 4) / 256, 256>>>(out);
}